// round 5
// baseline (speedup 1.0000x reference)
#include <cuda_runtime.h>
#include <cuda_bf16.h>
#include <cstdint>

#define BATCH 16
#define CIN   256
#define NPIX  4096   // 64*64
#define M3    768    // combined q,k,v output channels
#define KP    768    // split-K total (hi*hi + hi*lo + lo*hi)
#define KX    512    // x-split storage k length (hi 256 | lo 256)

// Scratch (device globals; no allocations allowed)
__device__ float         g_qkv[(size_t)BATCH * M3 * NPIX];        // 201 MB fp32 qkv
__device__ __nv_bfloat16 g_xs [(size_t)BATCH * NPIX * KX];        // 67 MB  x split, [b][p][kx]
__device__ __nv_bfloat16 g_ws [(size_t)M3 * KP];                  // 1.2 MB w split, [o][k']

__device__ __forceinline__ uint32_t s2u(const void* p) {
    uint32_t a;
    asm("{ .reg .u64 t; cvta.to.shared.u64 t, %1; cvt.u32.u64 %0, t; }" : "=r"(a) : "l"(p));
    return a;
}

#define SWZ(off) ((off) ^ (((off) >> 3) & 0x70))

__device__ __forceinline__ void cp_async16(uint32_t dst, const void* src) {
    asm volatile("cp.async.cg.shared.global [%0], [%1], 16;" :: "r"(dst), "l"(src));
}

__device__ __forceinline__ void ldmatrix_x4(uint32_t* r, uint32_t addr) {
    asm volatile("ldmatrix.sync.aligned.m8n8.x4.shared.b16 {%0,%1,%2,%3}, [%4];"
                 : "=r"(r[0]), "=r"(r[1]), "=r"(r[2]), "=r"(r[3]) : "r"(addr));
}

__device__ __forceinline__ void mma16816(float* c, const uint32_t* a, uint32_t b0, uint32_t b1) {
    asm volatile(
        "mma.sync.aligned.m16n8k16.row.col.f32.bf16.bf16.f32 "
        "{%0,%1,%2,%3}, {%4,%5,%6,%7}, {%8,%9}, {%0,%1,%2,%3};"
        : "+f"(c[0]), "+f"(c[1]), "+f"(c[2]), "+f"(c[3])
        : "r"(a[0]), "r"(a[1]), "r"(a[2]), "r"(a[3]), "r"(b0), "r"(b1));
}

// ---------------------------------------------------------------------------
// Kernel A: split x -> bf16 hi/lo, transposed to [b][p][kx] (kx: hi 0..255, lo 256..511)
// ---------------------------------------------------------------------------
__global__ __launch_bounds__(256) void split_x_kernel(const float* __restrict__ x) {
    __shared__ float s[64][65];
    const int b = blockIdx.z, c0 = blockIdx.y * 64, p0 = blockIdx.x * 64;
    const float* xb = x + ((size_t)b * CIN + c0) * NPIX + p0;
    const int t = threadIdx.x;
#pragma unroll
    for (int i = 0; i < 16; i++) {
        int idx = t + 256 * i;
        int c = idx >> 6, p = idx & 63;
        s[c][p] = xb[(size_t)c * NPIX + p];
    }
    __syncthreads();
    __nv_bfloat16* xs = g_xs + ((size_t)b * NPIX + p0) * KX + c0;
#pragma unroll
    for (int i = 0; i < 16; i++) {
        int idx = t + 256 * i;
        int cc = idx & 63, p = idx >> 6;
        float v = s[cc][p];
        __nv_bfloat16 h = __float2bfloat16(v);
        __nv_bfloat16 l = __float2bfloat16(v - __bfloat162float(h));
        xs[(size_t)p * KX + cc]       = h;
        xs[(size_t)p * KX + 256 + cc] = l;
    }
}

// ---------------------------------------------------------------------------
// Kernel B: split weights -> W' = [w_hi(256) | w_hi(256) | w_lo(256)] per row, [o][k']
// ---------------------------------------------------------------------------
__global__ __launch_bounds__(256) void split_w_kernel(
    const float* __restrict__ wq, const float* __restrict__ wk, const float* __restrict__ wv) {
    int idx = blockIdx.x * 256 + threadIdx.x;   // 768*768 total
    int o = idx / KP, kp = idx - o * KP;
    const float* w = (o < 256) ? wq : (o < 512) ? wk : wv;
    int ol = o & 255;
    int c  = (kp < 256) ? kp : (kp < 512) ? kp - 256 : kp - 512;
    float v = w[ol * CIN + c];
    __nv_bfloat16 h = __float2bfloat16(v);
    g_ws[idx] = (kp < 512) ? h : __float2bfloat16(v - __bfloat162float(h));
}

// ---------------------------------------------------------------------------
// Kernel C: HMMA bf16 GEMM (unchanged from round 3).
// ---------------------------------------------------------------------------
#define BM 128
#define BN 128
#define BK 64
#define NIT 12
#define STAGE_BYTES (BM * BK * 2 + BN * BK * 2)   // 32 KB (A then B)

extern __shared__ __align__(1024) char dynsmem[];

__global__ __launch_bounds__(256) void qkv_mma_kernel(
    const float* __restrict__ bq, const float* __restrict__ bk, const float* __restrict__ bv)
{
    const int t    = threadIdx.x;
    const int lane = t & 31;
    const int warp = t >> 5;
    const int wm   = warp & 3;     // 4 warps along M: 32 rows each
    const int wn   = warp >> 2;    // 2 warps along N: 64 cols each

    const int b  = blockIdx.z;
    const int o0 = blockIdx.y * BM;
    const int p0 = blockIdx.x * BN;

    const uint32_t smemBase = s2u(dynsmem);

    const __nv_bfloat16* Wb = g_ws + (size_t)o0 * KP;
    const __nv_bfloat16* Xb = g_xs + ((size_t)b * NPIX + p0) * KX;

    float c[2][8][4];
#pragma unroll
    for (int i = 0; i < 2; i++)
#pragma unroll
        for (int j = 0; j < 8; j++)
#pragma unroll
            for (int k = 0; k < 4; k++) c[i][j][k] = 0.f;

    auto load_stage = [&](int it, int s) {
        const int ka = it * BK;
        const int kb = (it < 8) ? it * BK : (it - 8) * BK;
        const uint32_t aB = smemBase + s * STAGE_BYTES;
        const uint32_t bB = aB + BM * BK * 2;
#pragma unroll
        for (int j = 0; j < 4; j++) {
            int idx = t + 256 * j;
            int row = idx >> 3, c16 = idx & 7;
            cp_async16(aB + SWZ(row * 128 + c16 * 16),
                       (const char*)(Wb + (size_t)row * KP + ka) + c16 * 16);
        }
#pragma unroll
        for (int j = 0; j < 4; j++) {
            int idx = t + 256 * j;
            int row = idx >> 3, c16 = idx & 7;
            cp_async16(bB + SWZ(row * 128 + c16 * 16),
                       (const char*)(Xb + (size_t)row * KX + kb) + c16 * 16);
        }
        asm volatile("cp.async.commit_group;");
    };

    auto compute_stage = [&](int s) {
        const uint32_t aB = smemBase + s * STAGE_BYTES;
        const uint32_t bB = aB + BM * BK * 2;
#pragma unroll
        for (int ks = 0; ks < 4; ks++) {
            uint32_t af[2][4];
#pragma unroll
            for (int mt = 0; mt < 2; mt++) {
                int row = wm * 32 + mt * 16 + (lane & 15);
                int col = ks * 32 + (lane >> 4) * 16;
                ldmatrix_x4(af[mt], aB + SWZ(row * 128 + col));
            }
            uint32_t bf[4][4];
#pragma unroll
            for (int np = 0; np < 4; np++) {
                int row = wn * 64 + np * 16 + (lane & 7) + ((lane >> 4) << 3);
                int col = ks * 32 + ((lane >> 3) & 1) * 16;
                ldmatrix_x4(bf[np], bB + SWZ(row * 128 + col));
            }
#pragma unroll
            for (int mt = 0; mt < 2; mt++)
#pragma unroll
                for (int np = 0; np < 4; np++) {
                    mma16816(c[mt][np * 2 + 0], af[mt], bf[np][0], bf[np][1]);
                    mma16816(c[mt][np * 2 + 1], af[mt], bf[np][2], bf[np][3]);
                }
        }
    };

    load_stage(0, 0);
    for (int it = 0; it < NIT; ++it) {
        if (it + 1 < NIT) load_stage(it + 1, (it + 1) & 1);
        if (it + 1 < NIT) asm volatile("cp.async.wait_group 1;" ::: "memory");
        else              asm volatile("cp.async.wait_group 0;" ::: "memory");
        __syncthreads();
        compute_stage(it & 1);
        __syncthreads();
    }

    float* outB = g_qkv + (size_t)b * M3 * NPIX;
#pragma unroll
    for (int mt = 0; mt < 2; mt++) {
        int r0 = o0 + wm * 32 + mt * 16 + (lane >> 2);
        int r1 = r0 + 8;
        const float* bp0 = (r0 < 256) ? bq : (r0 < 512) ? bk : bv;
        const float* bp1 = (r1 < 256) ? bq : (r1 < 512) ? bk : bv;
        float bias0 = bp0[r0 & 255];
        float bias1 = bp1[r1 & 255];
#pragma unroll
        for (int nt = 0; nt < 8; nt++) {
            int col = p0 + wn * 64 + nt * 8 + (lane & 3) * 2;
            float2 v0 = make_float2(c[mt][nt][0] + bias0, c[mt][nt][1] + bias0);
            float2 v1 = make_float2(c[mt][nt][2] + bias1, c[mt][nt][3] + bias1);
            *(float2*)(outB + (size_t)r0 * NPIX + col) = v0;
            *(float2*)(outB + (size_t)r1 * NPIX + col) = v1;
        }
    }
}

// ---------------------------------------------------------------------------
// Kernel D: attention, 64 threads/block, 8x8 register microtile, stride 68
// (float4-aligned rows). Scatter stores staggered to reduce bank conflicts.
// X1 = qT[w][h] -> Pt[g][h];  X2 = kT[w][g] -> V[g][w].
// ---------------------------------------------------------------------------
#define AST 68

__global__ __launch_bounds__(64) void attn_kernel(float* __restrict__ out)
{
    __shared__ float X1[64][AST];
    __shared__ float X2[64][AST];

    const int blk = blockIdx.x;
    const int b   = blk >> 8;
    const int o   = blk & 255;

    const float* qp = g_qkv + ((size_t)b * M3 + o) * NPIX;
    const float* kp = qp + (size_t)256 * NPIX;
    const float* vp = qp + (size_t)512 * NPIX;

    const int t  = threadIdx.x;   // 0..63
    const int tx = t & 7;         // owns cols tx*8..tx*8+7
    const int ty = t >> 3;        // owns rows ty*8..ty*8+7
    const int rot = (t >> 1) & 3; // scatter-store stagger

    // Load q,k transposed into smem (coalesced float4 global reads,
    // component order rotated per-lane -> ~2-way instead of 8-way STS conflict).
#pragma unroll
    for (int it = 0; it < 16; it++) {
        int flat = it * 256 + t * 4;
        int h = flat >> 6, w = flat & 63;
        float4 qv = *(const float4*)(qp + flat);
        float4 kv = *(const float4*)(kp + flat);
        float qa[4] = {qv.x, qv.y, qv.z, qv.w};
        float ka[4] = {kv.x, kv.y, kv.z, kv.w};
#pragma unroll
        for (int cc = 0; cc < 4; cc++) {
            int cidx = (cc + rot) & 3;
            X1[w + cidx][h] = qa[cidx];
            X2[w + cidx][h] = ka[cidx];
        }
    }
    __syncthreads();

    // S[h][g] = sum_w qT[w][h] * kT[w][g]   (8x8 microtile)
    float s[8][8];
#pragma unroll
    for (int i = 0; i < 8; i++)
#pragma unroll
        for (int j = 0; j < 8; j++) s[i][j] = 0.f;

#pragma unroll 4
    for (int w = 0; w < 64; w++) {
        float a[8], bb[8];
        *(float4*)(a)      = *(const float4*)(&X1[w][ty * 8]);
        *(float4*)(a + 4)  = *(const float4*)(&X1[w][ty * 8 + 4]);
        *(float4*)(bb)     = *(const float4*)(&X2[w][tx * 8]);
        *(float4*)(bb + 4) = *(const float4*)(&X2[w][tx * 8 + 4]);
#pragma unroll
        for (int i = 0; i < 8; i++)
#pragma unroll
            for (int j = 0; j < 8; j++)
                s[i][j] = fmaf(a[i], bb[j], s[i][j]);
    }

    // Softmax over g. Row h = ty*8+i owned by 8 consecutive lanes (same ty).
    const float scale = 0.17677669529663687f;  // 1/sqrt(32)
#pragma unroll
    for (int i = 0; i < 8; i++) {
        float m = -1e30f;
#pragma unroll
        for (int j = 0; j < 8; j++) { s[i][j] *= scale; m = fmaxf(m, s[i][j]); }
#pragma unroll
        for (int off = 4; off > 0; off >>= 1)
            m = fmaxf(m, __shfl_xor_sync(0xffffffffu, m, off, 8));
        float sum = 0.f;
#pragma unroll
        for (int j = 0; j < 8; j++) { s[i][j] = __expf(s[i][j] - m); sum += s[i][j]; }
#pragma unroll
        for (int off = 4; off > 0; off >>= 1)
            sum += __shfl_xor_sync(0xffffffffu, sum, off, 8);
        float inv = 1.f / sum;
#pragma unroll
        for (int j = 0; j < 8; j++) s[i][j] *= inv;
    }

    __syncthreads();   // everyone done reading X1/X2

    // X1 <- P transposed: Pt[g][h]  (j-order rotated by tx -> 4-way max)
#pragma unroll
    for (int jj = 0; jj < 8; jj++) {
        int j = (jj + tx) & 7;
#pragma unroll
        for (int i = 0; i < 8; i++)
            X1[tx * 8 + j][ty * 8 + i] = s[i][j];
    }
    // X2 <- V natural: V[g][w]  (consecutive float4 -> conflict-free)
#pragma unroll
    for (int it = 0; it < 16; it++) {
        int flat = it * 256 + t * 4;
        int g = flat >> 6, w = flat & 63;
        float4 vv = *(const float4*)(vp + flat);
        *(float4*)(&X2[g][w]) = vv;
    }
    __syncthreads();

    // ctx[h][w] = sum_g Pt[g][h] * V[g][w]
    float c[8][8];
#pragma unroll
    for (int i = 0; i < 8; i++)
#pragma unroll
        for (int j = 0; j < 8; j++) c[i][j] = 0.f;

#pragma unroll 4
    for (int g = 0; g < 64; g++) {
        float a[8], bb[8];
        *(float4*)(a)      = *(const float4*)(&X1[g][ty * 8]);
        *(float4*)(a + 4)  = *(const float4*)(&X1[g][ty * 8 + 4]);
        *(float4*)(bb)     = *(const float4*)(&X2[g][tx * 8]);
        *(float4*)(bb + 4) = *(const float4*)(&X2[g][tx * 8 + 4]);
#pragma unroll
        for (int i = 0; i < 8; i++)
#pragma unroll
            for (int j = 0; j < 8; j++)
                c[i][j] = fmaf(a[i], bb[j], c[i][j]);
    }

    float* op = out + ((size_t)b * 256 + o) * NPIX;
#pragma unroll
    for (int i = 0; i < 8; i++) {
        float4 v0 = make_float4(c[i][0], c[i][1], c[i][2], c[i][3]);
        float4 v1 = make_float4(c[i][4], c[i][5], c[i][6], c[i][7]);
        float* row = op + (size_t)(ty * 8 + i) * 64 + tx * 8;
        *(float4*)(row)     = v0;
        *(float4*)(row + 4) = v1;
    }
}

extern "C" void kernel_launch(void* const* d_in, const int* in_sizes, int n_in,
                              void* d_out, int out_size)
{
    const float* x  = (const float*)d_in[0];
    const float* wq = (const float*)d_in[1];
    const float* bq = (const float*)d_in[2];
    const float* wk = (const float*)d_in[3];
    const float* bk = (const float*)d_in[4];
    const float* wv = (const float*)d_in[5];
    const float* bv = (const float*)d_in[6];
    float* out = (float*)d_out;

    cudaFuncSetAttribute(qkv_mma_kernel, cudaFuncAttributeMaxDynamicSharedMemorySize,
                         2 * STAGE_BYTES);

    split_x_kernel<<<dim3(NPIX / 64, CIN / 64, BATCH), 256>>>(x);
    split_w_kernel<<<(M3 * KP) / 256, 256>>>(wq, wk, wv);
    qkv_mma_kernel<<<dim3(NPIX / BN, M3 / BM, BATCH), 256, 2 * STAGE_BYTES>>>(bq, bk, bv);
    attn_kernel<<<BATCH * 256, 64>>>(out);
}

// round 6
// speedup vs baseline: 1.5531x; 1.5531x over previous
#include <cuda_runtime.h>
#include <cuda_bf16.h>
#include <cstdint>

#define BATCH 16
#define CIN   256
#define NPIX  4096   // 64*64
#define M3    768    // combined q,k,v output channels
#define KP    768    // split-K total (hi*hi + hi*lo + lo*hi)
#define KX    512    // x-split storage k length (hi 256 | lo 256)

// Scratch (device globals; no allocations allowed)
__device__ float         g_qkv[(size_t)BATCH * M3 * NPIX];        // 201 MB fp32 qkv
__device__ __nv_bfloat16 g_xs [(size_t)BATCH * NPIX * KX];        // 67 MB  x split, [b][p][kx]
__device__ __nv_bfloat16 g_ws [(size_t)M3 * KP];                  // 1.2 MB w split, [o][k']

__device__ __forceinline__ uint32_t s2u(const void* p) {
    uint32_t a;
    asm("{ .reg .u64 t; cvta.to.shared.u64 t, %1; cvt.u32.u64 %0, t; }" : "=r"(a) : "l"(p));
    return a;
}

#define SWZ(off) ((off) ^ (((off) >> 3) & 0x70))

__device__ __forceinline__ void cp_async16(uint32_t dst, const void* src) {
    asm volatile("cp.async.cg.shared.global [%0], [%1], 16;" :: "r"(dst), "l"(src));
}

__device__ __forceinline__ void ldmatrix_x4(uint32_t* r, uint32_t addr) {
    asm volatile("ldmatrix.sync.aligned.m8n8.x4.shared.b16 {%0,%1,%2,%3}, [%4];"
                 : "=r"(r[0]), "=r"(r[1]), "=r"(r[2]), "=r"(r[3]) : "r"(addr));
}

__device__ __forceinline__ void mma16816(float* c, const uint32_t* a, uint32_t b0, uint32_t b1) {
    asm volatile(
        "mma.sync.aligned.m16n8k16.row.col.f32.bf16.bf16.f32 "
        "{%0,%1,%2,%3}, {%4,%5,%6,%7}, {%8,%9}, {%0,%1,%2,%3};"
        : "+f"(c[0]), "+f"(c[1]), "+f"(c[2]), "+f"(c[3])
        : "r"(a[0]), "r"(a[1]), "r"(a[2]), "r"(a[3]), "r"(b0), "r"(b1));
}

__device__ __forceinline__ uint32_t packbf(float a, float b) {
    __nv_bfloat162 t;
    t.x = __float2bfloat16(a);
    t.y = __float2bfloat16(b);
    return *(uint32_t*)&t;
}

// ---------------------------------------------------------------------------
// Kernel A: split x -> bf16 hi/lo, transposed to [b][p][kx] (kx: hi 0..255, lo 256..511)
// ---------------------------------------------------------------------------
__global__ __launch_bounds__(256) void split_x_kernel(const float* __restrict__ x) {
    __shared__ float s[64][65];
    const int b = blockIdx.z, c0 = blockIdx.y * 64, p0 = blockIdx.x * 64;
    const float* xb = x + ((size_t)b * CIN + c0) * NPIX + p0;
    const int t = threadIdx.x;
#pragma unroll
    for (int i = 0; i < 16; i++) {
        int idx = t + 256 * i;
        int c = idx >> 6, p = idx & 63;
        s[c][p] = xb[(size_t)c * NPIX + p];
    }
    __syncthreads();
    __nv_bfloat16* xs = g_xs + ((size_t)b * NPIX + p0) * KX + c0;
#pragma unroll
    for (int i = 0; i < 16; i++) {
        int idx = t + 256 * i;
        int cc = idx & 63, p = idx >> 6;
        float v = s[cc][p];
        __nv_bfloat16 h = __float2bfloat16(v);
        __nv_bfloat16 l = __float2bfloat16(v - __bfloat162float(h));
        xs[(size_t)p * KX + cc]       = h;
        xs[(size_t)p * KX + 256 + cc] = l;
    }
}

// ---------------------------------------------------------------------------
// Kernel B: split weights -> W' = [w_hi(256) | w_hi(256) | w_lo(256)] per row, [o][k']
// ---------------------------------------------------------------------------
__global__ __launch_bounds__(256) void split_w_kernel(
    const float* __restrict__ wq, const float* __restrict__ wk, const float* __restrict__ wv) {
    int idx = blockIdx.x * 256 + threadIdx.x;   // 768*768 total
    int o = idx / KP, kp = idx - o * KP;
    const float* w = (o < 256) ? wq : (o < 512) ? wk : wv;
    int ol = o & 255;
    int c  = (kp < 256) ? kp : (kp < 512) ? kp - 256 : kp - 512;
    float v = w[ol * CIN + c];
    __nv_bfloat16 h = __float2bfloat16(v);
    g_ws[idx] = (kp < 512) ? h : __float2bfloat16(v - __bfloat162float(h));
}

// ---------------------------------------------------------------------------
// Kernel C: HMMA bf16 GEMM (unchanged from round 3).
// ---------------------------------------------------------------------------
#define BM 128
#define BN 128
#define BK 64
#define NIT 12
#define STAGE_BYTES (BM * BK * 2 + BN * BK * 2)   // 32 KB (A then B)

extern __shared__ __align__(1024) char dynsmem[];

__global__ __launch_bounds__(256) void qkv_mma_kernel(
    const float* __restrict__ bq, const float* __restrict__ bk, const float* __restrict__ bv)
{
    const int t    = threadIdx.x;
    const int lane = t & 31;
    const int warp = t >> 5;
    const int wm   = warp & 3;     // 4 warps along M: 32 rows each
    const int wn   = warp >> 2;    // 2 warps along N: 64 cols each

    const int b  = blockIdx.z;
    const int o0 = blockIdx.y * BM;
    const int p0 = blockIdx.x * BN;

    const uint32_t smemBase = s2u(dynsmem);

    const __nv_bfloat16* Wb = g_ws + (size_t)o0 * KP;
    const __nv_bfloat16* Xb = g_xs + ((size_t)b * NPIX + p0) * KX;

    float c[2][8][4];
#pragma unroll
    for (int i = 0; i < 2; i++)
#pragma unroll
        for (int j = 0; j < 8; j++)
#pragma unroll
            for (int k = 0; k < 4; k++) c[i][j][k] = 0.f;

    auto load_stage = [&](int it, int s) {
        const int ka = it * BK;
        const int kb = (it < 8) ? it * BK : (it - 8) * BK;
        const uint32_t aB = smemBase + s * STAGE_BYTES;
        const uint32_t bB = aB + BM * BK * 2;
#pragma unroll
        for (int j = 0; j < 4; j++) {
            int idx = t + 256 * j;
            int row = idx >> 3, c16 = idx & 7;
            cp_async16(aB + SWZ(row * 128 + c16 * 16),
                       (const char*)(Wb + (size_t)row * KP + ka) + c16 * 16);
        }
#pragma unroll
        for (int j = 0; j < 4; j++) {
            int idx = t + 256 * j;
            int row = idx >> 3, c16 = idx & 7;
            cp_async16(bB + SWZ(row * 128 + c16 * 16),
                       (const char*)(Xb + (size_t)row * KX + kb) + c16 * 16);
        }
        asm volatile("cp.async.commit_group;");
    };

    auto compute_stage = [&](int s) {
        const uint32_t aB = smemBase + s * STAGE_BYTES;
        const uint32_t bB = aB + BM * BK * 2;
#pragma unroll
        for (int ks = 0; ks < 4; ks++) {
            uint32_t af[2][4];
#pragma unroll
            for (int mt = 0; mt < 2; mt++) {
                int row = wm * 32 + mt * 16 + (lane & 15);
                int col = ks * 32 + (lane >> 4) * 16;
                ldmatrix_x4(af[mt], aB + SWZ(row * 128 + col));
            }
            uint32_t bf[4][4];
#pragma unroll
            for (int np = 0; np < 4; np++) {
                int row = wn * 64 + np * 16 + (lane & 7) + ((lane >> 4) << 3);
                int col = ks * 32 + ((lane >> 3) & 1) * 16;
                ldmatrix_x4(bf[np], bB + SWZ(row * 128 + col));
            }
#pragma unroll
            for (int mt = 0; mt < 2; mt++)
#pragma unroll
                for (int np = 0; np < 4; np++) {
                    mma16816(c[mt][np * 2 + 0], af[mt], bf[np][0], bf[np][1]);
                    mma16816(c[mt][np * 2 + 1], af[mt], bf[np][2], bf[np][3]);
                }
        }
    };

    load_stage(0, 0);
    for (int it = 0; it < NIT; ++it) {
        if (it + 1 < NIT) load_stage(it + 1, (it + 1) & 1);
        if (it + 1 < NIT) asm volatile("cp.async.wait_group 1;" ::: "memory");
        else              asm volatile("cp.async.wait_group 0;" ::: "memory");
        __syncthreads();
        compute_stage(it & 1);
        __syncthreads();
    }

    float* outB = g_qkv + (size_t)b * M3 * NPIX;
#pragma unroll
    for (int mt = 0; mt < 2; mt++) {
        int r0 = o0 + wm * 32 + mt * 16 + (lane >> 2);
        int r1 = r0 + 8;
        const float* bp0 = (r0 < 256) ? bq : (r0 < 512) ? bk : bv;
        const float* bp1 = (r1 < 256) ? bq : (r1 < 512) ? bk : bv;
        float bias0 = bp0[r0 & 255];
        float bias1 = bp1[r1 & 255];
#pragma unroll
        for (int nt = 0; nt < 8; nt++) {
            int col = p0 + wn * 64 + nt * 8 + (lane & 3) * 2;
            float2 v0 = make_float2(c[mt][nt][0] + bias0, c[mt][nt][1] + bias0);
            float2 v1 = make_float2(c[mt][nt][2] + bias1, c[mt][nt][3] + bias1);
            *(float2*)(outB + (size_t)r0 * NPIX + col) = v0;
            *(float2*)(outB + (size_t)r1 * NPIX + col) = v1;
        }
    }
}

// ---------------------------------------------------------------------------
// Kernel D: attention on HMMA with bf16x3 split precision.
// One block = one (b, o) pair. 128 threads = 4 warps, warp wy owns rows wy*16..+15.
// smem (dynamic, 48 KB): q_hi q_lo k_hi k_lo vt_hi vt_lo, each 64x64 bf16 SW128.
// S = Qhi Khi^T + Qhi Klo^T + Qlo Khi^T; softmax on fragments;
// P split -> reuse q buffers; ctx = Phi Vhi + Phi Vlo + Plo Vhi.
// ---------------------------------------------------------------------------
#define A_QHI 0
#define A_QLO 8192
#define A_KHI 16384
#define A_KLO 24576
#define A_VHI 32768
#define A_VLO 40960
#define ATTN_SMEM 49152

__global__ __launch_bounds__(128) void attn_kernel(float* __restrict__ out)
{
    const int t    = threadIdx.x;
    const int lane = t & 31;
    const int wy   = t >> 5;          // warp -> rows wy*16..wy*16+15

    const int blk = blockIdx.x;
    const int b   = blk >> 8;
    const int o   = blk & 255;

    const float* qp = g_qkv + ((size_t)b * M3 + o) * NPIX;
    const float* kp = qp + (size_t)256 * NPIX;
    const float* vp = qp + (size_t)512 * NPIX;

    const uint32_t sb = s2u(dynsmem);

    // ---- Convert Q,K (natural [h][w]) and V (transposed [w][g]) to bf16 hi/lo ----
#pragma unroll
    for (int i = 0; i < 8; i++) {
        int flat = t * 4 + i * 512;
        int h = flat >> 6, w = flat & 63;     // w multiple of 4
        float4 qv = *(const float4*)(qp + flat);
        float4 kv = *(const float4*)(kp + flat);
        float4 vv = *(const float4*)(vp + flat);

        float qa[4] = {qv.x, qv.y, qv.z, qv.w};
        float ka[4] = {kv.x, kv.y, kv.z, kv.w};
        float va[4] = {vv.x, vv.y, vv.z, vv.w};

        float qh[4], ql[4], kh[4], kl[4];
#pragma unroll
        for (int j = 0; j < 4; j++) {
            __nv_bfloat16 hq = __float2bfloat16(qa[j]);
            qh[j] = __bfloat162float(hq);  ql[j] = qa[j] - qh[j];
            __nv_bfloat16 hk = __float2bfloat16(ka[j]);
            kh[j] = __bfloat162float(hk);  kl[j] = ka[j] - kh[j];
        }
        uint32_t off = SWZ(h * 128 + w * 2);
        *(uint2*)(dynsmem + A_QHI + off) = make_uint2(packbf(qh[0], qh[1]), packbf(qh[2], qh[3]));
        *(uint2*)(dynsmem + A_QLO + off) = make_uint2(packbf(ql[0], ql[1]), packbf(ql[2], ql[3]));
        *(uint2*)(dynsmem + A_KHI + off) = make_uint2(packbf(kh[0], kh[1]), packbf(kh[2], kh[3]));
        *(uint2*)(dynsmem + A_KLO + off) = make_uint2(packbf(kl[0], kl[1]), packbf(kl[2], kl[3]));

        // V transposed: vt[w+j][g=h]
#pragma unroll
        for (int j = 0; j < 4; j++) {
            __nv_bfloat16 hv = __float2bfloat16(va[j]);
            float lv = va[j] - __bfloat162float(hv);
            uint32_t voff = SWZ((w + j) * 128 + h * 2);
            *(__nv_bfloat16*)(dynsmem + A_VHI + voff) = hv;
            *(__nv_bfloat16*)(dynsmem + A_VLO + voff) = __float2bfloat16(lv);
        }
    }
    __syncthreads();

    // ---- S = Q K^T with 3-term bf16 split ----
    float cS[8][4];
#pragma unroll
    for (int n = 0; n < 8; n++)
#pragma unroll
        for (int k = 0; k < 4; k++) cS[n][k] = 0.f;

#pragma unroll
    for (int ks = 0; ks < 4; ks++) {
        uint32_t ahi[4], alo[4];
        {
            int row = wy * 16 + (lane & 15);
            int col = ks * 32 + (lane >> 4) * 16;
            ldmatrix_x4(ahi, sb + A_QHI + SWZ(row * 128 + col));
            ldmatrix_x4(alo, sb + A_QLO + SWZ(row * 128 + col));
        }
#pragma unroll
        for (int np = 0; np < 4; np++) {
            uint32_t bhi[4], blo[4];
            int row = np * 16 + (lane & 7) + ((lane >> 4) << 3);
            int col = ks * 32 + ((lane >> 3) & 1) * 16;
            ldmatrix_x4(bhi, sb + A_KHI + SWZ(row * 128 + col));
            ldmatrix_x4(blo, sb + A_KLO + SWZ(row * 128 + col));
            mma16816(cS[np * 2 + 0], ahi, bhi[0], bhi[1]);
            mma16816(cS[np * 2 + 1], ahi, bhi[2], bhi[3]);
            mma16816(cS[np * 2 + 0], ahi, blo[0], blo[1]);
            mma16816(cS[np * 2 + 1], ahi, blo[2], blo[3]);
            mma16816(cS[np * 2 + 0], alo, bhi[0], bhi[1]);
            mma16816(cS[np * 2 + 1], alo, bhi[2], bhi[3]);
        }
    }

    // ---- softmax on fragments ----
    // thread holds: rows r0 = wy*16 + (lane>>2) (c[0],c[1]) and r0+8 (c[2],c[3]),
    // cols nn*8 + 2*(lane&3) + {0,1}. Row spread over lanes with same lane>>2.
    const float scale = 0.17677669529663687f;  // 1/sqrt(32)
    float m0 = -1e30f, m1 = -1e30f;
#pragma unroll
    for (int n = 0; n < 8; n++) {
#pragma unroll
        for (int k = 0; k < 4; k++) cS[n][k] *= scale;
        m0 = fmaxf(m0, fmaxf(cS[n][0], cS[n][1]));
        m1 = fmaxf(m1, fmaxf(cS[n][2], cS[n][3]));
    }
    m0 = fmaxf(m0, __shfl_xor_sync(0xffffffffu, m0, 1));
    m0 = fmaxf(m0, __shfl_xor_sync(0xffffffffu, m0, 2));
    m1 = fmaxf(m1, __shfl_xor_sync(0xffffffffu, m1, 1));
    m1 = fmaxf(m1, __shfl_xor_sync(0xffffffffu, m1, 2));

    float s0 = 0.f, s1 = 0.f;
#pragma unroll
    for (int n = 0; n < 8; n++) {
        cS[n][0] = __expf(cS[n][0] - m0);
        cS[n][1] = __expf(cS[n][1] - m0);
        cS[n][2] = __expf(cS[n][2] - m1);
        cS[n][3] = __expf(cS[n][3] - m1);
        s0 += cS[n][0] + cS[n][1];
        s1 += cS[n][2] + cS[n][3];
    }
    s0 += __shfl_xor_sync(0xffffffffu, s0, 1);
    s0 += __shfl_xor_sync(0xffffffffu, s0, 2);
    s1 += __shfl_xor_sync(0xffffffffu, s1, 1);
    s1 += __shfl_xor_sync(0xffffffffu, s1, 2);
    const float inv0 = 1.f / s0, inv1 = 1.f / s1;

    __syncthreads();   // all ldmatrix reads of q buffers done; safe to overwrite

    // ---- store P (hi/lo) into the q buffers, same A-operand layout ----
    {
        int r0 = wy * 16 + (lane >> 2);
        int col2 = (lane & 3) * 4;                 // byte offset of col pair within 16B chunk
#pragma unroll
        for (int n = 0; n < 8; n++) {
            float p0 = cS[n][0] * inv0, p1 = cS[n][1] * inv0;
            float p2 = cS[n][2] * inv1, p3 = cS[n][3] * inv1;
            __nv_bfloat16 h0 = __float2bfloat16(p0), h1 = __float2bfloat16(p1);
            __nv_bfloat16 h2 = __float2bfloat16(p2), h3 = __float2bfloat16(p3);
            uint32_t off0 = SWZ(r0 * 128 + n * 16 + col2);
            uint32_t off1 = SWZ((r0 + 8) * 128 + n * 16 + col2);
            __nv_bfloat162 H0; H0.x = h0; H0.y = h1;
            __nv_bfloat162 L0; L0.x = __float2bfloat16(p0 - __bfloat162float(h0));
                               L0.y = __float2bfloat16(p1 - __bfloat162float(h1));
            __nv_bfloat162 H1; H1.x = h2; H1.y = h3;
            __nv_bfloat162 L1; L1.x = __float2bfloat16(p2 - __bfloat162float(h2));
                               L1.y = __float2bfloat16(p3 - __bfloat162float(h3));
            *(__nv_bfloat162*)(dynsmem + A_QHI + off0) = H0;
            *(__nv_bfloat162*)(dynsmem + A_QLO + off0) = L0;
            *(__nv_bfloat162*)(dynsmem + A_QHI + off1) = H1;
            *(__nv_bfloat162*)(dynsmem + A_QLO + off1) = L1;
        }
    }
    __syncthreads();

    // ---- ctx = P V with 3-term split (A = P in q buffers, B = Vt) ----
    float cC[8][4];
#pragma unroll
    for (int n = 0; n < 8; n++)
#pragma unroll
        for (int k = 0; k < 4; k++) cC[n][k] = 0.f;

#pragma unroll
    for (int ks = 0; ks < 4; ks++) {
        uint32_t ahi[4], alo[4];
        {
            int row = wy * 16 + (lane & 15);
            int col = ks * 32 + (lane >> 4) * 16;
            ldmatrix_x4(ahi, sb + A_QHI + SWZ(row * 128 + col));
            ldmatrix_x4(alo, sb + A_QLO + SWZ(row * 128 + col));
        }
#pragma unroll
        for (int np = 0; np < 4; np++) {
            uint32_t bhi[4], blo[4];
            int row = np * 16 + (lane & 7) + ((lane >> 4) << 3);
            int col = ks * 32 + ((lane >> 3) & 1) * 16;
            ldmatrix_x4(bhi, sb + A_VHI + SWZ(row * 128 + col));
            ldmatrix_x4(blo, sb + A_VLO + SWZ(row * 128 + col));
            mma16816(cC[np * 2 + 0], ahi, bhi[0], bhi[1]);
            mma16816(cC[np * 2 + 1], ahi, bhi[2], bhi[3]);
            mma16816(cC[np * 2 + 0], ahi, blo[0], blo[1]);
            mma16816(cC[np * 2 + 1], ahi, blo[2], blo[3]);
            mma16816(cC[np * 2 + 0], alo, bhi[0], bhi[1]);
            mma16816(cC[np * 2 + 1], alo, bhi[2], bhi[3]);
        }
    }

    // ---- epilogue ----
    float* op = out + ((size_t)b * 256 + o) * NPIX;
    int r0 = wy * 16 + (lane >> 2);
    int cb = (lane & 3) * 2;
#pragma unroll
    for (int n = 0; n < 8; n++) {
        *(float2*)(op + (size_t)r0 * 64 + n * 8 + cb)       = make_float2(cC[n][0], cC[n][1]);
        *(float2*)(op + (size_t)(r0 + 8) * 64 + n * 8 + cb) = make_float2(cC[n][2], cC[n][3]);
    }
}

extern "C" void kernel_launch(void* const* d_in, const int* in_sizes, int n_in,
                              void* d_out, int out_size)
{
    const float* x  = (const float*)d_in[0];
    const float* wq = (const float*)d_in[1];
    const float* bq = (const float*)d_in[2];
    const float* wk = (const float*)d_in[3];
    const float* bk = (const float*)d_in[4];
    const float* wv = (const float*)d_in[5];
    const float* bv = (const float*)d_in[6];
    float* out = (float*)d_out;

    cudaFuncSetAttribute(qkv_mma_kernel, cudaFuncAttributeMaxDynamicSharedMemorySize,
                         2 * STAGE_BYTES);
    cudaFuncSetAttribute(attn_kernel, cudaFuncAttributeMaxDynamicSharedMemorySize,
                         ATTN_SMEM);

    split_x_kernel<<<dim3(NPIX / 64, CIN / 64, BATCH), 256>>>(x);
    split_w_kernel<<<(M3 * KP) / 256, 256>>>(wq, wk, wv);
    qkv_mma_kernel<<<dim3(NPIX / BN, M3 / BM, BATCH), 256, 2 * STAGE_BYTES>>>(bq, bk, bv);
    attn_kernel<<<BATCH * 256, 128, ATTN_SMEM>>>(out);
}

// round 7
// speedup vs baseline: 1.6676x; 1.0737x over previous
#include <cuda_runtime.h>
#include <cuda_bf16.h>
#include <cstdint>

#define BATCH 16
#define CIN   256
#define NPIX  4096   // 64*64
#define M3    768    // combined q,k,v output channels
#define KP    768    // split-K total (hi*hi + hi*lo + lo*hi)
#define KX    512    // x-split storage k length (hi 256 | lo 256)

// Scratch (device globals; no allocations allowed)
__device__ float         g_qkv[(size_t)BATCH * M3 * NPIX];        // 201 MB fp32 qkv
__device__ __nv_bfloat16 g_xs [(size_t)BATCH * NPIX * KX];        // 67 MB  x split, [b][p][kx]
__device__ __nv_bfloat16 g_ws [(size_t)M3 * KP];                  // 1.2 MB w split, [o][k']

__device__ __forceinline__ uint32_t s2u(const void* p) {
    uint32_t a;
    asm("{ .reg .u64 t; cvta.to.shared.u64 t, %1; cvt.u32.u64 %0, t; }" : "=r"(a) : "l"(p));
    return a;
}

#define SWZ(off) ((off) ^ (((off) >> 3) & 0x70))

__device__ __forceinline__ void cp_async16(uint32_t dst, const void* src) {
    asm volatile("cp.async.cg.shared.global [%0], [%1], 16;" :: "r"(dst), "l"(src));
}

__device__ __forceinline__ void ldmatrix_x4(uint32_t* r, uint32_t addr) {
    asm volatile("ldmatrix.sync.aligned.m8n8.x4.shared.b16 {%0,%1,%2,%3}, [%4];"
                 : "=r"(r[0]), "=r"(r[1]), "=r"(r[2]), "=r"(r[3]) : "r"(addr));
}

__device__ __forceinline__ void ldmatrix_x4_trans(uint32_t* r, uint32_t addr) {
    asm volatile("ldmatrix.sync.aligned.m8n8.x4.trans.shared.b16 {%0,%1,%2,%3}, [%4];"
                 : "=r"(r[0]), "=r"(r[1]), "=r"(r[2]), "=r"(r[3]) : "r"(addr));
}

__device__ __forceinline__ void mma16816(float* c, const uint32_t* a, uint32_t b0, uint32_t b1) {
    asm volatile(
        "mma.sync.aligned.m16n8k16.row.col.f32.bf16.bf16.f32 "
        "{%0,%1,%2,%3}, {%4,%5,%6,%7}, {%8,%9}, {%0,%1,%2,%3};"
        : "+f"(c[0]), "+f"(c[1]), "+f"(c[2]), "+f"(c[3])
        : "r"(a[0]), "r"(a[1]), "r"(a[2]), "r"(a[3]), "r"(b0), "r"(b1));
}

__device__ __forceinline__ uint32_t packbf(float a, float b) {
    __nv_bfloat162 t;
    t.x = __float2bfloat16(a);
    t.y = __float2bfloat16(b);
    return *(uint32_t*)&t;
}

// ---------------------------------------------------------------------------
// Kernel A: split x -> bf16 hi/lo, transposed to [b][p][kx] (kx: hi 0..255, lo 256..511)
// ---------------------------------------------------------------------------
__global__ __launch_bounds__(256) void split_x_kernel(const float* __restrict__ x) {
    __shared__ float s[64][65];
    const int b = blockIdx.z, c0 = blockIdx.y * 64, p0 = blockIdx.x * 64;
    const float* xb = x + ((size_t)b * CIN + c0) * NPIX + p0;
    const int t = threadIdx.x;
#pragma unroll
    for (int i = 0; i < 16; i++) {
        int idx = t + 256 * i;
        int c = idx >> 6, p = idx & 63;
        s[c][p] = xb[(size_t)c * NPIX + p];
    }
    __syncthreads();
    __nv_bfloat16* xs = g_xs + ((size_t)b * NPIX + p0) * KX + c0;
#pragma unroll
    for (int i = 0; i < 16; i++) {
        int idx = t + 256 * i;
        int cc = idx & 63, p = idx >> 6;
        float v = s[cc][p];
        __nv_bfloat16 h = __float2bfloat16(v);
        __nv_bfloat16 l = __float2bfloat16(v - __bfloat162float(h));
        xs[(size_t)p * KX + cc]       = h;
        xs[(size_t)p * KX + 256 + cc] = l;
    }
}

// ---------------------------------------------------------------------------
// Kernel B: split weights -> W' = [w_hi(256) | w_hi(256) | w_lo(256)] per row, [o][k']
// ---------------------------------------------------------------------------
__global__ __launch_bounds__(256) void split_w_kernel(
    const float* __restrict__ wq, const float* __restrict__ wk, const float* __restrict__ wv) {
    int idx = blockIdx.x * 256 + threadIdx.x;   // 768*768 total
    int o = idx / KP, kp = idx - o * KP;
    const float* w = (o < 256) ? wq : (o < 512) ? wk : wv;
    int ol = o & 255;
    int c  = (kp < 256) ? kp : (kp < 512) ? kp - 256 : kp - 512;
    float v = w[ol * CIN + c];
    __nv_bfloat16 h = __float2bfloat16(v);
    g_ws[idx] = (kp < 512) ? h : __float2bfloat16(v - __bfloat162float(h));
}

// ---------------------------------------------------------------------------
// Kernel C: HMMA bf16 GEMM, 3-stage cp.async pipeline, 1 barrier per iter.
// ---------------------------------------------------------------------------
#define BM 128
#define BN 128
#define BK 64
#define NIT 12
#define STAGE_BYTES (BM * BK * 2 + BN * BK * 2)   // 32 KB (A then B)
#define NSTAGE 3

extern __shared__ __align__(1024) char dynsmem[];

__global__ __launch_bounds__(256) void qkv_mma_kernel(
    const float* __restrict__ bq, const float* __restrict__ bk, const float* __restrict__ bv)
{
    const int t    = threadIdx.x;
    const int lane = t & 31;
    const int warp = t >> 5;
    const int wm   = warp & 3;     // 4 warps along M: 32 rows each
    const int wn   = warp >> 2;    // 2 warps along N: 64 cols each

    const int b  = blockIdx.z;
    const int o0 = blockIdx.y * BM;
    const int p0 = blockIdx.x * BN;

    const uint32_t smemBase = s2u(dynsmem);

    const __nv_bfloat16* Wb = g_ws + (size_t)o0 * KP;
    const __nv_bfloat16* Xb = g_xs + ((size_t)b * NPIX + p0) * KX;

    float c[2][8][4];
#pragma unroll
    for (int i = 0; i < 2; i++)
#pragma unroll
        for (int j = 0; j < 8; j++)
#pragma unroll
            for (int k = 0; k < 4; k++) c[i][j][k] = 0.f;

    auto load_stage = [&](int it) {
        const int ka = it * BK;
        const int kb = (it < 8) ? it * BK : (it - 8) * BK;
        const uint32_t aB = smemBase + (it % NSTAGE) * STAGE_BYTES;
        const uint32_t bB = aB + BM * BK * 2;
#pragma unroll
        for (int j = 0; j < 4; j++) {
            int idx = t + 256 * j;
            int row = idx >> 3, c16 = idx & 7;
            cp_async16(aB + SWZ(row * 128 + c16 * 16),
                       (const char*)(Wb + (size_t)row * KP + ka) + c16 * 16);
        }
#pragma unroll
        for (int j = 0; j < 4; j++) {
            int idx = t + 256 * j;
            int row = idx >> 3, c16 = idx & 7;
            cp_async16(bB + SWZ(row * 128 + c16 * 16),
                       (const char*)(Xb + (size_t)row * KX + kb) + c16 * 16);
        }
        asm volatile("cp.async.commit_group;");
    };

    auto compute_stage = [&](int it) {
        const uint32_t aB = smemBase + (it % NSTAGE) * STAGE_BYTES;
        const uint32_t bB = aB + BM * BK * 2;
#pragma unroll
        for (int ks = 0; ks < 4; ks++) {
            uint32_t af[2][4];
#pragma unroll
            for (int mt = 0; mt < 2; mt++) {
                int row = wm * 32 + mt * 16 + (lane & 15);
                int col = ks * 32 + (lane >> 4) * 16;
                ldmatrix_x4(af[mt], aB + SWZ(row * 128 + col));
            }
            uint32_t bf[4][4];
#pragma unroll
            for (int np = 0; np < 4; np++) {
                int row = wn * 64 + np * 16 + (lane & 7) + ((lane >> 4) << 3);
                int col = ks * 32 + ((lane >> 3) & 1) * 16;
                ldmatrix_x4(bf[np], bB + SWZ(row * 128 + col));
            }
#pragma unroll
            for (int mt = 0; mt < 2; mt++)
#pragma unroll
                for (int np = 0; np < 4; np++) {
                    mma16816(c[mt][np * 2 + 0], af[mt], bf[np][0], bf[np][1]);
                    mma16816(c[mt][np * 2 + 1], af[mt], bf[np][2], bf[np][3]);
                }
        }
    };

    load_stage(0);
    load_stage(1);
    for (int it = 0; it < NIT; ++it) {
        if (it == NIT - 1) asm volatile("cp.async.wait_group 0;" ::: "memory");
        else               asm volatile("cp.async.wait_group 1;" ::: "memory");
        __syncthreads();                 // stage it ready; buffer (it-1)%3 free
        if (it + 2 < NIT) load_stage(it + 2);
        compute_stage(it);
    }

    float* outB = g_qkv + (size_t)b * M3 * NPIX;
#pragma unroll
    for (int mt = 0; mt < 2; mt++) {
        int r0 = o0 + wm * 32 + mt * 16 + (lane >> 2);
        int r1 = r0 + 8;
        const float* bp0 = (r0 < 256) ? bq : (r0 < 512) ? bk : bv;
        const float* bp1 = (r1 < 256) ? bq : (r1 < 512) ? bk : bv;
        float bias0 = bp0[r0 & 255];
        float bias1 = bp1[r1 & 255];
#pragma unroll
        for (int nt = 0; nt < 8; nt++) {
            int col = p0 + wn * 64 + nt * 8 + (lane & 3) * 2;
            float2 v0 = make_float2(c[mt][nt][0] + bias0, c[mt][nt][1] + bias0);
            float2 v1 = make_float2(c[mt][nt][2] + bias1, c[mt][nt][3] + bias1);
            *(float2*)(outB + (size_t)r0 * NPIX + col) = v0;
            *(float2*)(outB + (size_t)r1 * NPIX + col) = v1;
        }
    }
}

// ---------------------------------------------------------------------------
// Kernel D: attention on HMMA with bf16x3 split precision.
// V now stored NATURAL [g][w] (vectorized hi/lo stores); PV B-operand loaded
// with ldmatrix.x4.trans (k=g rows, n=w cols). Everything else as round 6.
// ---------------------------------------------------------------------------
#define A_QHI 0
#define A_QLO 8192
#define A_KHI 16384
#define A_KLO 24576
#define A_VHI 32768
#define A_VLO 40960
#define ATTN_SMEM 49152

__global__ __launch_bounds__(128) void attn_kernel(float* __restrict__ out)
{
    const int t    = threadIdx.x;
    const int lane = t & 31;
    const int wy   = t >> 5;          // warp -> rows wy*16..wy*16+15

    const int blk = blockIdx.x;
    const int b   = blk >> 8;
    const int o   = blk & 255;

    const float* qp = g_qkv + ((size_t)b * M3 + o) * NPIX;
    const float* kp = qp + (size_t)256 * NPIX;
    const float* vp = qp + (size_t)512 * NPIX;

    const uint32_t sb = s2u(dynsmem);

    // ---- Convert Q,K,V (all natural [row][w]) to bf16 hi/lo, vectorized ----
#pragma unroll
    for (int i = 0; i < 8; i++) {
        int flat = t * 4 + i * 512;
        int h = flat >> 6, w = flat & 63;     // w multiple of 4
        float4 qv = *(const float4*)(qp + flat);
        float4 kv = *(const float4*)(kp + flat);
        float4 vv = *(const float4*)(vp + flat);

        float qa[4] = {qv.x, qv.y, qv.z, qv.w};
        float ka[4] = {kv.x, kv.y, kv.z, kv.w};
        float va[4] = {vv.x, vv.y, vv.z, vv.w};

        float qh[4], ql[4], kh[4], kl[4], vh[4], vl[4];
#pragma unroll
        for (int j = 0; j < 4; j++) {
            __nv_bfloat16 hq = __float2bfloat16(qa[j]);
            qh[j] = __bfloat162float(hq);  ql[j] = qa[j] - qh[j];
            __nv_bfloat16 hk = __float2bfloat16(ka[j]);
            kh[j] = __bfloat162float(hk);  kl[j] = ka[j] - kh[j];
            __nv_bfloat16 hv = __float2bfloat16(va[j]);
            vh[j] = __bfloat162float(hv);  vl[j] = va[j] - vh[j];
        }
        uint32_t off = SWZ(h * 128 + w * 2);
        *(uint2*)(dynsmem + A_QHI + off) = make_uint2(packbf(qh[0], qh[1]), packbf(qh[2], qh[3]));
        *(uint2*)(dynsmem + A_QLO + off) = make_uint2(packbf(ql[0], ql[1]), packbf(ql[2], ql[3]));
        *(uint2*)(dynsmem + A_KHI + off) = make_uint2(packbf(kh[0], kh[1]), packbf(kh[2], kh[3]));
        *(uint2*)(dynsmem + A_KLO + off) = make_uint2(packbf(kl[0], kl[1]), packbf(kl[2], kl[3]));
        *(uint2*)(dynsmem + A_VHI + off) = make_uint2(packbf(vh[0], vh[1]), packbf(vh[2], vh[3]));
        *(uint2*)(dynsmem + A_VLO + off) = make_uint2(packbf(vl[0], vl[1]), packbf(vl[2], vl[3]));
    }
    __syncthreads();

    // ---- S = Q K^T with 3-term bf16 split ----
    float cS[8][4];
#pragma unroll
    for (int n = 0; n < 8; n++)
#pragma unroll
        for (int k = 0; k < 4; k++) cS[n][k] = 0.f;

#pragma unroll
    for (int ks = 0; ks < 4; ks++) {
        uint32_t ahi[4], alo[4];
        {
            int row = wy * 16 + (lane & 15);
            int col = ks * 32 + (lane >> 4) * 16;
            ldmatrix_x4(ahi, sb + A_QHI + SWZ(row * 128 + col));
            ldmatrix_x4(alo, sb + A_QLO + SWZ(row * 128 + col));
        }
#pragma unroll
        for (int np = 0; np < 4; np++) {
            uint32_t bhi[4], blo[4];
            int row = np * 16 + (lane & 7) + ((lane >> 4) << 3);
            int col = ks * 32 + ((lane >> 3) & 1) * 16;
            ldmatrix_x4(bhi, sb + A_KHI + SWZ(row * 128 + col));
            ldmatrix_x4(blo, sb + A_KLO + SWZ(row * 128 + col));
            mma16816(cS[np * 2 + 0], ahi, bhi[0], bhi[1]);
            mma16816(cS[np * 2 + 1], ahi, bhi[2], bhi[3]);
            mma16816(cS[np * 2 + 0], ahi, blo[0], blo[1]);
            mma16816(cS[np * 2 + 1], ahi, blo[2], blo[3]);
            mma16816(cS[np * 2 + 0], alo, bhi[0], bhi[1]);
            mma16816(cS[np * 2 + 1], alo, bhi[2], bhi[3]);
        }
    }

    // ---- softmax on fragments ----
    const float scale = 0.17677669529663687f;  // 1/sqrt(32)
    float m0 = -1e30f, m1 = -1e30f;
#pragma unroll
    for (int n = 0; n < 8; n++) {
#pragma unroll
        for (int k = 0; k < 4; k++) cS[n][k] *= scale;
        m0 = fmaxf(m0, fmaxf(cS[n][0], cS[n][1]));
        m1 = fmaxf(m1, fmaxf(cS[n][2], cS[n][3]));
    }
    m0 = fmaxf(m0, __shfl_xor_sync(0xffffffffu, m0, 1));
    m0 = fmaxf(m0, __shfl_xor_sync(0xffffffffu, m0, 2));
    m1 = fmaxf(m1, __shfl_xor_sync(0xffffffffu, m1, 1));
    m1 = fmaxf(m1, __shfl_xor_sync(0xffffffffu, m1, 2));

    float s0 = 0.f, s1 = 0.f;
#pragma unroll
    for (int n = 0; n < 8; n++) {
        cS[n][0] = __expf(cS[n][0] - m0);
        cS[n][1] = __expf(cS[n][1] - m0);
        cS[n][2] = __expf(cS[n][2] - m1);
        cS[n][3] = __expf(cS[n][3] - m1);
        s0 += cS[n][0] + cS[n][1];
        s1 += cS[n][2] + cS[n][3];
    }
    s0 += __shfl_xor_sync(0xffffffffu, s0, 1);
    s0 += __shfl_xor_sync(0xffffffffu, s0, 2);
    s1 += __shfl_xor_sync(0xffffffffu, s1, 1);
    s1 += __shfl_xor_sync(0xffffffffu, s1, 2);
    const float inv0 = 1.f / s0, inv1 = 1.f / s1;

    __syncthreads();   // all ldmatrix reads of q buffers done; safe to overwrite

    // ---- store P (hi/lo) into the q buffers, same A-operand layout ----
    {
        int r0 = wy * 16 + (lane >> 2);
        int col2 = (lane & 3) * 4;                 // byte offset of col pair within 16B chunk
#pragma unroll
        for (int n = 0; n < 8; n++) {
            float p0 = cS[n][0] * inv0, p1 = cS[n][1] * inv0;
            float p2 = cS[n][2] * inv1, p3 = cS[n][3] * inv1;
            __nv_bfloat16 h0 = __float2bfloat16(p0), h1 = __float2bfloat16(p1);
            __nv_bfloat16 h2 = __float2bfloat16(p2), h3 = __float2bfloat16(p3);
            uint32_t off0 = SWZ(r0 * 128 + n * 16 + col2);
            uint32_t off1 = SWZ((r0 + 8) * 128 + n * 16 + col2);
            __nv_bfloat162 H0; H0.x = h0; H0.y = h1;
            __nv_bfloat162 L0; L0.x = __float2bfloat16(p0 - __bfloat162float(h0));
                               L0.y = __float2bfloat16(p1 - __bfloat162float(h1));
            __nv_bfloat162 H1; H1.x = h2; H1.y = h3;
            __nv_bfloat162 L1; L1.x = __float2bfloat16(p2 - __bfloat162float(h2));
                               L1.y = __float2bfloat16(p3 - __bfloat162float(h3));
            *(__nv_bfloat162*)(dynsmem + A_QHI + off0) = H0;
            *(__nv_bfloat162*)(dynsmem + A_QLO + off0) = L0;
            *(__nv_bfloat162*)(dynsmem + A_QHI + off1) = H1;
            *(__nv_bfloat162*)(dynsmem + A_QLO + off1) = L1;
        }
    }
    __syncthreads();

    // ---- ctx = P V with 3-term split; B via ldmatrix.trans on natural V ----
    float cC[8][4];
#pragma unroll
    for (int n = 0; n < 8; n++)
#pragma unroll
        for (int k = 0; k < 4; k++) cC[n][k] = 0.f;

#pragma unroll
    for (int ks = 0; ks < 4; ks++) {
        uint32_t ahi[4], alo[4];
        {
            int row = wy * 16 + (lane & 15);
            int col = ks * 32 + (lane >> 4) * 16;
            ldmatrix_x4(ahi, sb + A_QHI + SWZ(row * 128 + col));
            ldmatrix_x4(alo, sb + A_QLO + SWZ(row * 128 + col));
        }
#pragma unroll
        for (int np = 0; np < 4; np++) {
            uint32_t bhi[4], blo[4];
            // source rows = g (k-dim), cols = w (n-dim); trans swaps per 8x8 block
            int row = ks * 16 + (lane & 7) + ((lane >> 3) & 1) * 8;
            int colb = np * 32 + (lane >> 4) * 16;
            ldmatrix_x4_trans(bhi, sb + A_VHI + SWZ(row * 128 + colb));
            ldmatrix_x4_trans(blo, sb + A_VLO + SWZ(row * 128 + colb));
            mma16816(cC[np * 2 + 0], ahi, bhi[0], bhi[1]);
            mma16816(cC[np * 2 + 1], ahi, bhi[2], bhi[3]);
            mma16816(cC[np * 2 + 0], ahi, blo[0], blo[1]);
            mma16816(cC[np * 2 + 1], ahi, blo[2], blo[3]);
            mma16816(cC[np * 2 + 0], alo, bhi[0], bhi[1]);
            mma16816(cC[np * 2 + 1], alo, bhi[2], bhi[3]);
        }
    }

    // ---- epilogue ----
    float* op = out + ((size_t)b * 256 + o) * NPIX;
    int r0 = wy * 16 + (lane >> 2);
    int cb = (lane & 3) * 2;
#pragma unroll
    for (int n = 0; n < 8; n++) {
        *(float2*)(op + (size_t)r0 * 64 + n * 8 + cb)       = make_float2(cC[n][0], cC[n][1]);
        *(float2*)(op + (size_t)(r0 + 8) * 64 + n * 8 + cb) = make_float2(cC[n][2], cC[n][3]);
    }
}

extern "C" void kernel_launch(void* const* d_in, const int* in_sizes, int n_in,
                              void* d_out, int out_size)
{
    const float* x  = (const float*)d_in[0];
    const float* wq = (const float*)d_in[1];
    const float* bq = (const float*)d_in[2];
    const float* wk = (const float*)d_in[3];
    const float* bk = (const float*)d_in[4];
    const float* wv = (const float*)d_in[5];
    const float* bv = (const float*)d_in[6];
    float* out = (float*)d_out;

    cudaFuncSetAttribute(qkv_mma_kernel, cudaFuncAttributeMaxDynamicSharedMemorySize,
                         NSTAGE * STAGE_BYTES);
    cudaFuncSetAttribute(attn_kernel, cudaFuncAttributeMaxDynamicSharedMemorySize,
                         ATTN_SMEM);

    split_x_kernel<<<dim3(NPIX / 64, CIN / 64, BATCH), 256>>>(x);
    split_w_kernel<<<(M3 * KP) / 256, 256>>>(wq, wk, wv);
    qkv_mma_kernel<<<dim3(NPIX / BN, M3 / BM, BATCH), 256, NSTAGE * STAGE_BYTES>>>(bq, bk, bv);
    attn_kernel<<<BATCH * 256, 128, ATTN_SMEM>>>(out);
}